// round 5
// baseline (speedup 1.0000x reference)
#include <cuda_runtime.h>
#include <cuda_bf16.h>
#include <cstdint>

// out[v, g, v2, d] = W[GE[v,g] % 3, d] + b[d]
//   GE: [512, 4, 1] int32, W: [3, 64] f32, b: [64] f32
//   out: [512, 4, 512, 64] f32  (256 MB) — constant along v2.
//
// 512 blocks x 4 (v,g) pairs. Each thread owns 8 floats of the 64-float row,
// streams copies via 256-bit st.global.cs.v8.b32 (evict-first: write-once
// stream, keep L2 writeback draining).

static constexpr int V = 512;
static constexpr int G = 4;
static constexpr int D = 64;
static constexpr int THREADS = 256;
static constexpr int CHUNKS = D / 8;                  // 8 threads per row
static constexpr int ROWS_PER_IT = THREADS / CHUNKS;  // 32 rows per iteration
static constexpr int PAIRS_PER_BLOCK = 4;

__device__ __forceinline__ void stg256_cs(float* p, const float v[8])
{
    asm volatile(
        "st.global.cs.v8.b32 [%0], {%1,%2,%3,%4,%5,%6,%7,%8};"
        :: "l"(p),
           "r"(__float_as_uint(v[0])), "r"(__float_as_uint(v[1])),
           "r"(__float_as_uint(v[2])), "r"(__float_as_uint(v[3])),
           "r"(__float_as_uint(v[4])), "r"(__float_as_uint(v[5])),
           "r"(__float_as_uint(v[6])), "r"(__float_as_uint(v[7]))
        : "memory");
}

__global__ void __launch_bounds__(THREADS, 8)
gembed_bcast_kernel(const int* __restrict__ GE,
                    const float* __restrict__ W,
                    const float* __restrict__ b,
                    float* __restrict__ out)
{
    const int t     = threadIdx.x;
    const int chunk = t & (CHUNKS - 1);    // which 8-float chunk of the row
    const int r0    = t >> 3;              // starting copy row (0..31)

    const float4 b0 = reinterpret_cast<const float4*>(b)[chunk * 2 + 0];
    const float4 b1 = reinterpret_cast<const float4*>(b)[chunk * 2 + 1];

    #pragma unroll
    for (int pp = 0; pp < PAIRS_PER_BLOCK; pp++) {
        const int pair = blockIdx.x * PAIRS_PER_BLOCK + pp;
        const int idx  = GE[pair] % 3;

        const float4 w0 = reinterpret_cast<const float4*>(W + idx * D)[chunk * 2 + 0];
        const float4 w1 = reinterpret_cast<const float4*>(W + idx * D)[chunk * 2 + 1];

        float val[8];
        val[0] = w0.x + b0.x;  val[1] = w0.y + b0.y;
        val[2] = w0.z + b0.z;  val[3] = w0.w + b0.w;
        val[4] = w1.x + b1.x;  val[5] = w1.y + b1.y;
        val[6] = w1.z + b1.z;  val[7] = w1.w + b1.w;

        float* base = out + (size_t)pair * (size_t)(V * D) + (size_t)(chunk * 8);

        #pragma unroll
        for (int r = r0; r < V; r += ROWS_PER_IT) {
            stg256_cs(base + r * D, val);
        }
    }
}

extern "C" void kernel_launch(void* const* d_in, const int* in_sizes, int n_in,
                              void* d_out, int out_size)
{
    const int*   GE = (const int*)d_in[0];
    const float* W  = (const float*)d_in[1];
    const float* b  = (const float*)d_in[2];
    float* out = (float*)d_out;

    (void)in_sizes; (void)n_in; (void)out_size;

    gembed_bcast_kernel<<<(V * G) / PAIRS_PER_BLOCK, THREADS>>>(GE, W, b, out);
}

// round 6
// speedup vs baseline: 1.1551x; 1.1551x over previous
#include <cuda_runtime.h>
#include <cuda_bf16.h>
#include <cstdint>

// out[v, g, v2, d] = W[GE[v,g] % 3, d] + b[d]
//   GE: [512, 4, 1] int32, W: [3, 64] f32, b: [64] f32
//   out: [512, 4, 512, 64] f32  (256 MB) — constant along v2.
//
// Best config (R3): one block per (v,g) pair (2048 blocks, occ ~73%), each
// thread owns 8 floats of the row, streams 16 copies via 256-bit stores.
// This round: st.global.cg (L2-only) to skip the L1 stage of the store path.

static constexpr int V = 512;
static constexpr int G = 4;
static constexpr int D = 64;
static constexpr int THREADS = 256;
static constexpr int CHUNKS = D / 8;                  // 8 threads per row
static constexpr int ROWS_PER_IT = THREADS / CHUNKS;  // 32 rows per iteration

__device__ __forceinline__ void stg256_cg(float* p, const float v[8])
{
    asm volatile(
        "st.global.cg.v8.b32 [%0], {%1,%2,%3,%4,%5,%6,%7,%8};"
        :: "l"(p),
           "r"(__float_as_uint(v[0])), "r"(__float_as_uint(v[1])),
           "r"(__float_as_uint(v[2])), "r"(__float_as_uint(v[3])),
           "r"(__float_as_uint(v[4])), "r"(__float_as_uint(v[5])),
           "r"(__float_as_uint(v[6])), "r"(__float_as_uint(v[7]))
        : "memory");
}

__global__ void __launch_bounds__(THREADS, 8)
gembed_bcast_kernel(const int* __restrict__ GE,
                    const float* __restrict__ W,
                    const float* __restrict__ b,
                    float* __restrict__ out)
{
    const int pair  = blockIdx.x;          // v*G + g, 0..2047
    const int t     = threadIdx.x;         // 0..255
    const int chunk = t & (CHUNKS - 1);    // which 8-float chunk of the row
    const int r0    = t >> 3;              // starting copy row (0..31)

    const int idx = GE[pair] % 3;          // GE in [0,3)

    const float4 w0 = reinterpret_cast<const float4*>(W + idx * D)[chunk * 2 + 0];
    const float4 w1 = reinterpret_cast<const float4*>(W + idx * D)[chunk * 2 + 1];
    const float4 b0 = reinterpret_cast<const float4*>(b)[chunk * 2 + 0];
    const float4 b1 = reinterpret_cast<const float4*>(b)[chunk * 2 + 1];

    float val[8];
    val[0] = w0.x + b0.x;  val[1] = w0.y + b0.y;
    val[2] = w0.z + b0.z;  val[3] = w0.w + b0.w;
    val[4] = w1.x + b1.x;  val[5] = w1.y + b1.y;
    val[6] = w1.z + b1.z;  val[7] = w1.w + b1.w;

    // Stream 512 copies of the row: warp writes 1 KB contiguous per
    // instruction; each thread issues 16 x STG.256 (L2-only).
    float* base = out + (size_t)pair * (size_t)(V * D) + (size_t)(chunk * 8);

    #pragma unroll
    for (int r = r0; r < V; r += ROWS_PER_IT) {
        stg256_cg(base + r * D, val);
    }
}

extern "C" void kernel_launch(void* const* d_in, const int* in_sizes, int n_in,
                              void* d_out, int out_size)
{
    const int*   GE = (const int*)d_in[0];
    const float* W  = (const float*)d_in[1];
    const float* b  = (const float*)d_in[2];
    float* out = (float*)d_out;

    (void)in_sizes; (void)n_in; (void)out_size;

    gembed_bcast_kernel<<<V * G, THREADS>>>(GE, W, b, out);
}

// round 7
// speedup vs baseline: 1.1680x; 1.0112x over previous
#include <cuda_runtime.h>
#include <cuda_bf16.h>
#include <cstdint>

// out[v, g, v2, d] = W[GE[v,g] % 3, d] + b[d]
//   GE: [512, 4, 1] int32, W: [3, 64] f32, b: [64] f32
//   out: [512, 4, 512, 64] f32  (256 MB) — constant along v2.
//
// Finalization candidate: same store engine as the 43.5 us best (STG.256,
// occ ~73%), but 2 blocks per (v,g) pair (4096 blocks x 64 KB) to halve the
// work quantum and smooth the end-of-kernel wave tail.

static constexpr int V = 512;
static constexpr int G = 4;
static constexpr int D = 64;
static constexpr int THREADS = 256;
static constexpr int CHUNKS = D / 8;                  // 8 threads per row
static constexpr int ROWS_PER_IT = THREADS / CHUNKS;  // 32 rows per iteration
static constexpr int SPLIT = 2;                       // blocks per pair
static constexpr int ROWS_PER_BLOCK = V / SPLIT;      // 256 copy rows

__device__ __forceinline__ void stg256(float* p, const float v[8])
{
    asm volatile(
        "st.global.v8.b32 [%0], {%1,%2,%3,%4,%5,%6,%7,%8};"
        :: "l"(p),
           "r"(__float_as_uint(v[0])), "r"(__float_as_uint(v[1])),
           "r"(__float_as_uint(v[2])), "r"(__float_as_uint(v[3])),
           "r"(__float_as_uint(v[4])), "r"(__float_as_uint(v[5])),
           "r"(__float_as_uint(v[6])), "r"(__float_as_uint(v[7]))
        : "memory");
}

__global__ void __launch_bounds__(THREADS, 8)
gembed_bcast_kernel(const int* __restrict__ GE,
                    const float* __restrict__ W,
                    const float* __restrict__ b,
                    float* __restrict__ out)
{
    const int blk   = blockIdx.x;                 // 0..4095
    const int pair  = blk >> 1;                   // v*G + g
    const int half  = blk & 1;                    // which 256-row half
    const int t     = threadIdx.x;
    const int chunk = t & (CHUNKS - 1);           // 8-float chunk of the row
    const int r0    = t >> 3;                     // starting copy row (0..31)

    const int idx = GE[pair] % 3;                 // GE in [0,3)

    const float4 w0 = reinterpret_cast<const float4*>(W + idx * D)[chunk * 2 + 0];
    const float4 w1 = reinterpret_cast<const float4*>(W + idx * D)[chunk * 2 + 1];
    const float4 b0 = reinterpret_cast<const float4*>(b)[chunk * 2 + 0];
    const float4 b1 = reinterpret_cast<const float4*>(b)[chunk * 2 + 1];

    float val[8];
    val[0] = w0.x + b0.x;  val[1] = w0.y + b0.y;
    val[2] = w0.z + b0.z;  val[3] = w0.w + b0.w;
    val[4] = w1.x + b1.x;  val[5] = w1.y + b1.y;
    val[6] = w1.z + b1.z;  val[7] = w1.w + b1.w;

    // This block streams 256 copies (64 KB): 8 x STG.256 per thread.
    float* base = out + (size_t)pair * (size_t)(V * D)
                      + (size_t)half * (size_t)(ROWS_PER_BLOCK * D)
                      + (size_t)(chunk * 8);

    #pragma unroll
    for (int r = r0; r < ROWS_PER_BLOCK; r += ROWS_PER_IT) {
        stg256(base + r * D, val);
    }
}

extern "C" void kernel_launch(void* const* d_in, const int* in_sizes, int n_in,
                              void* d_out, int out_size)
{
    const int*   GE = (const int*)d_in[0];
    const float* W  = (const float*)d_in[1];
    const float* b  = (const float*)d_in[2];
    float* out = (float*)d_out;

    (void)in_sizes; (void)n_in; (void)out_size;

    gembed_bcast_kernel<<<V * G * SPLIT, THREADS>>>(GE, W, b, out);
}

// round 8
// speedup vs baseline: 1.2048x; 1.0314x over previous
#include <cuda_runtime.h>
#include <cuda_bf16.h>
#include <cstdint>

// out[v, g, v2, d] = W[GE[v,g] % 3, d] + b[d]
//   GE: [512, 4, 1] int32, W: [3, 64] f32, b: [64] f32
//   out: [512, 4, 512, 64] f32  (256 MB) — constant along v2.
//
// R7 showed drain rate rises with concurrent store-issuing CTAs:
// SPLIT 1->2 gave occ 73->82%, 5.04->5.21 TB/s. This round SPLIT=4:
// 8192 blocks x 32 KB, 4 x STG.256 per thread.

static constexpr int V = 512;
static constexpr int G = 4;
static constexpr int D = 64;
static constexpr int THREADS = 256;
static constexpr int CHUNKS = D / 8;                  // 8 threads per row
static constexpr int ROWS_PER_IT = THREADS / CHUNKS;  // 32 rows per iteration
static constexpr int SPLIT = 4;                       // blocks per pair
static constexpr int ROWS_PER_BLOCK = V / SPLIT;      // 128 copy rows

__device__ __forceinline__ void stg256(float* p, const float v[8])
{
    asm volatile(
        "st.global.v8.b32 [%0], {%1,%2,%3,%4,%5,%6,%7,%8};"
        :: "l"(p),
           "r"(__float_as_uint(v[0])), "r"(__float_as_uint(v[1])),
           "r"(__float_as_uint(v[2])), "r"(__float_as_uint(v[3])),
           "r"(__float_as_uint(v[4])), "r"(__float_as_uint(v[5])),
           "r"(__float_as_uint(v[6])), "r"(__float_as_uint(v[7]))
        : "memory");
}

__global__ void __launch_bounds__(THREADS, 8)
gembed_bcast_kernel(const int* __restrict__ GE,
                    const float* __restrict__ W,
                    const float* __restrict__ b,
                    float* __restrict__ out)
{
    const int blk   = blockIdx.x;                 // 0..8191
    const int pair  = blk >> 2;                   // v*G + g
    const int part  = blk & 3;                    // which 128-row quarter
    const int t     = threadIdx.x;
    const int chunk = t & (CHUNKS - 1);           // 8-float chunk of the row
    const int r0    = t >> 3;                     // starting copy row (0..31)

    const int idx = GE[pair] % 3;                 // GE in [0,3)

    const float4 w0 = reinterpret_cast<const float4*>(W + idx * D)[chunk * 2 + 0];
    const float4 w1 = reinterpret_cast<const float4*>(W + idx * D)[chunk * 2 + 1];
    const float4 b0 = reinterpret_cast<const float4*>(b)[chunk * 2 + 0];
    const float4 b1 = reinterpret_cast<const float4*>(b)[chunk * 2 + 1];

    float val[8];
    val[0] = w0.x + b0.x;  val[1] = w0.y + b0.y;
    val[2] = w0.z + b0.z;  val[3] = w0.w + b0.w;
    val[4] = w1.x + b1.x;  val[5] = w1.y + b1.y;
    val[6] = w1.z + b1.z;  val[7] = w1.w + b1.w;

    // This block streams 128 copies (32 KB): 4 x STG.256 per thread.
    float* base = out + (size_t)pair * (size_t)(V * D)
                      + (size_t)part * (size_t)(ROWS_PER_BLOCK * D)
                      + (size_t)(chunk * 8);

    #pragma unroll
    for (int r = r0; r < ROWS_PER_BLOCK; r += ROWS_PER_IT) {
        stg256(base + r * D, val);
    }
}

extern "C" void kernel_launch(void* const* d_in, const int* in_sizes, int n_in,
                              void* d_out, int out_size)
{
    const int*   GE = (const int*)d_in[0];
    const float* W  = (const float*)d_in[1];
    const float* b  = (const float*)d_in[2];
    float* out = (float*)d_out;

    (void)in_sizes; (void)n_in; (void)out_size;

    gembed_bcast_kernel<<<V * G * SPLIT, THREADS>>>(GE, W, b, out);
}

// round 10
// speedup vs baseline: 1.2057x; 1.0008x over previous
#include <cuda_runtime.h>
#include <cuda_bf16.h>
#include <cstdint>

// out[v, g, v2, d] = W[GE[v,g] % 3, d] + b[d]
//   GE: [512, 4, 1] int32, W: [3, 64] f32, b: [64] f32
//   out: [512, 4, 512, 64] f32  (256 MB) — constant along v2.
//
// Concurrency gradient: SPLIT 1->2->4 gave 5.04->5.21->5.38 TB/s.
// This round SPLIT=8: 16384 blocks x 16 KB, 2 x STG.256 per thread.

static constexpr int V = 512;
static constexpr int G = 4;
static constexpr int D = 64;
static constexpr int THREADS = 256;
static constexpr int CHUNKS = D / 8;                  // 8 threads per row
static constexpr int ROWS_PER_IT = THREADS / CHUNKS;  // 32 rows per iteration
static constexpr int SPLIT = 8;                       // blocks per pair
static constexpr int ROWS_PER_BLOCK = V / SPLIT;      // 64 copy rows

__device__ __forceinline__ void stg256(float* p, const float v[8])
{
    asm volatile(
        "st.global.v8.b32 [%0], {%1,%2,%3,%4,%5,%6,%7,%8};"
        :: "l"(p),
           "r"(__float_as_uint(v[0])), "r"(__float_as_uint(v[1])),
           "r"(__float_as_uint(v[2])), "r"(__float_as_uint(v[3])),
           "r"(__float_as_uint(v[4])), "r"(__float_as_uint(v[5])),
           "r"(__float_as_uint(v[6])), "r"(__float_as_uint(v[7]))
        : "memory");
}

__global__ void __launch_bounds__(THREADS, 8)
gembed_bcast_kernel(const int* __restrict__ GE,
                    const float* __restrict__ W,
                    const float* __restrict__ b,
                    float* __restrict__ out)
{
    const int blk   = blockIdx.x;                 // 0..16383
    const int pair  = blk >> 3;                   // v*G + g
    const int part  = blk & 7;                    // which 64-row slice
    const int t     = threadIdx.x;
    const int chunk = t & (CHUNKS - 1);           // 8-float chunk of the row
    const int r0    = t >> 3;                     // starting copy row (0..31)

    const int idx = GE[pair] % 3;                 // GE in [0,3)

    const float4 w0 = reinterpret_cast<const float4*>(W + idx * D)[chunk * 2 + 0];
    const float4 w1 = reinterpret_cast<const float4*>(W + idx * D)[chunk * 2 + 1];
    const float4 b0 = reinterpret_cast<const float4*>(b)[chunk * 2 + 0];
    const float4 b1 = reinterpret_cast<const float4*>(b)[chunk * 2 + 1];

    float val[8];
    val[0] = w0.x + b0.x;  val[1] = w0.y + b0.y;
    val[2] = w0.z + b0.z;  val[3] = w0.w + b0.w;
    val[4] = w1.x + b1.x;  val[5] = w1.y + b1.y;
    val[6] = w1.z + b1.z;  val[7] = w1.w + b1.w;

    // This block streams 64 copies (16 KB): 2 x STG.256 per thread.
    float* base = out + (size_t)pair * (size_t)(V * D)
                      + (size_t)part * (size_t)(ROWS_PER_BLOCK * D)
                      + (size_t)(chunk * 8);

    #pragma unroll
    for (int r = r0; r < ROWS_PER_BLOCK; r += ROWS_PER_IT) {
        stg256(base + r * D, val);
    }
}

extern "C" void kernel_launch(void* const* d_in, const int* in_sizes, int n_in,
                              void* d_out, int out_size)
{
    const int*   GE = (const int*)d_in[0];
    const float* W  = (const float*)d_in[1];
    const float* b  = (const float*)d_in[2];
    float* out = (float*)d_out;

    (void)in_sizes; (void)n_in; (void)out_size;

    gembed_bcast_kernel<<<V * G * SPLIT, THREADS>>>(GE, W, b, out);
}